// round 17
// baseline (speedup 1.0000x reference)
#include <cuda_runtime.h>
#include <math_constants.h>

// Sampler: B=256 rows, V=128000 vocab.
// inputs: logits [B,V] f32, temperatures [B] f32, uniform_noise [B,V] f32
// output: [tokens (B floats)] ++ [probs (B*V floats)]
//
// Geometry: 1 block/SM (148 resident rows -> 74MB evict_last set FITS L2),
// latency covered by deeper per-thread unrolling instead of a 2nd block.

#define NT 1024
#define BB 256
#define VV 128000
#define NV8 (VV / 8)                  // 16000 float8 chunks per row (pass 1)
#define NV4 (VV / 4)                  // 32000 float4 chunks per row (pass 2)
#define L2E 1.4426950408889634f
#define LN2 0.6931471805599453f

__device__ __forceinline__ float lg2a(float x) {
    float r; asm("lg2.approx.f32 %0, %1;" : "=f"(r) : "f"(x)); return r;
}
__device__ __forceinline__ float ex2a(float x) {
    float r; asm("ex2.approx.f32 %0, %1;" : "=f"(r) : "f"(x)); return r;
}
// 32-byte logits load, pinned toward L2 retention for the pass-2 reread.
// (sm_103a ptxas requires .v8.b32/.v4.b64 with L2::evict_last)
__device__ __forceinline__ void ldg_el8(const float* p, float v[8]) {
    unsigned long long a0, a1, a2, a3;
    asm("ld.global.L2::evict_last.v4.b64 {%0,%1,%2,%3}, [%4];"
        : "=l"(a0), "=l"(a1), "=l"(a2), "=l"(a3) : "l"(p));
    v[0] = __uint_as_float((unsigned)(a0));  v[1] = __uint_as_float((unsigned)(a0 >> 32));
    v[2] = __uint_as_float((unsigned)(a1));  v[3] = __uint_as_float((unsigned)(a1 >> 32));
    v[4] = __uint_as_float((unsigned)(a2));  v[5] = __uint_as_float((unsigned)(a2 >> 32));
    v[6] = __uint_as_float((unsigned)(a3));  v[7] = __uint_as_float((unsigned)(a3 >> 32));
}

// pass-1 element body: identical arithmetic to the proven R8 kernel
#define P1_BODY(JJ, LV)                                                        \
    _Pragma("unroll")                                                          \
    for (int h = 0; h < 2; h++) {                                              \
        const float4 n4 = __ldcs((const float4*)(nrow + 8 * (JJ)) + h);        \
        const float nv[4] = {n4.x, n4.y, n4.z, n4.w};                          \
        _Pragma("unroll")                                                      \
        for (int k = 0; k < 4; k++) {                                          \
            const int idx = 8 * (JJ) + 4 * h + k;                              \
            const float l = LV[4 * h + k];                                     \
            const float u = nv[k];                                             \
            if (l > gv) {                                                      \
                s = s * ex2a((gv - l) * a) + 1.0f;                             \
                gv = l; gi = idx;                                              \
            } else {                                                           \
                s += ex2a((l - gv) * a);                                       \
            }                                                                  \
            float y = (-LN2) * lg2a(u);                                        \
            const float d = 1.0f - u;                                          \
            if (u > 0.99f)                                                     \
                y = d * fmaf(d, fmaf(d, 0.33333333f, 0.5f), 1.0f);             \
            const float z = fmaf(lg2a(y), -LN2, l * inv_t);                    \
            if (z > sv) { sv = z; si = idx; }                                  \
        }                                                                      \
    }

#define P2_BODY(JJ)                                                            \
    {                                                                          \
        const float4 l4 = lrow4[(JJ)];                                         \
        float4 p;                                                              \
        p.x = ex2a(fmaf(l4.x, a, c)); p.y = ex2a(fmaf(l4.y, a, c));            \
        p.z = ex2a(fmaf(l4.z, a, c)); p.w = ex2a(fmaf(l4.w, a, c));            \
        __stcs(prow + (JJ), p);                                                \
    }

__global__ void __launch_bounds__(NT, 1)   // 1 block/SM: 64-reg budget, 148 resident rows
sampler_kernel(const float* __restrict__ logits,
               const float* __restrict__ temps,
               const float* __restrict__ noise,
               float* __restrict__ out)
{
    const int b    = blockIdx.x;
    const int tid  = threadIdx.x;
    const int lane = tid & 31;
    const int wid  = tid >> 5;            // 0..31

    const float t      = temps[b];
    const float safe_t = (t == 0.0f) ? 1.0f : t;
    const float inv_t  = 1.0f / safe_t;
    const float a      = inv_t * L2E;     // logit -> log2-domain scale

    const float* __restrict__ lrow = logits + (size_t)b * VV;
    const float* __restrict__ nrow = noise  + (size_t)b * VV;
    float4* __restrict__ prow      = (float4*)(out + BB + (size_t)b * VV);

    // pass 1: greedy argmax + Gumbel argmax + online exp-sum (base = running gv)
    // x2-unrolled: two independent 32B logits loads in flight per thread.
    float gv = -CUDART_INF_F; int gi = 0;
    float sv = -CUDART_INF_F; int si = 0;
    float s  = 0.0f;

    int j = tid;
    for (; j < NV8 - NT; j += 2 * NT) {   // both j and j+NT valid
        float lva[8], lvb[8];
        ldg_el8(lrow + 8 * j, lva);
        ldg_el8(lrow + 8 * (j + NT), lvb);
        P1_BODY(j, lva)
        P1_BODY(j + NT, lvb)
    }
    for (; j < NV8; j += NT) {
        float lv[8];
        ldg_el8(lrow + 8 * j, lv);
        P1_BODY(j, lv)
    }

    // ---- block reductions ----
    __shared__ float sh_gv[32]; __shared__ int sh_gi[32];
    __shared__ float sh_sv[32]; __shared__ int sh_si[32];
    __shared__ float sh_sum[32];
    __shared__ float fin_c;

    #pragma unroll
    for (int off = 16; off; off >>= 1) {
        float v  = __shfl_xor_sync(0xffffffffu, gv, off);
        int   i  = __shfl_xor_sync(0xffffffffu, gi, off);
        float ws = __shfl_xor_sync(0xffffffffu, s, off);
        if (v > gv) { s = fmaf(s, ex2a((gv - v) * a), ws); gv = v; gi = i; }
        else {
            s = fmaf(ws, ex2a((v - gv) * a), s);
            if (v == gv && i < gi) gi = i;
        }
        float v2 = __shfl_xor_sync(0xffffffffu, sv, off);
        int   i2 = __shfl_xor_sync(0xffffffffu, si, off);
        if (v2 > sv || (v2 == sv && i2 < si)) { sv = v2; si = i2; }
    }
    if (lane == 0) {
        sh_gv[wid] = gv; sh_gi[wid] = gi; sh_sum[wid] = s;
        sh_sv[wid] = sv; sh_si[wid] = si;
    }
    __syncthreads();

    if (wid == 0) {
        float v = sh_gv[lane]; int i = sh_gi[lane]; float c = sh_sum[lane];
        float v2 = sh_sv[lane]; int i2 = sh_si[lane];
        #pragma unroll
        for (int off = 16; off; off >>= 1) {
            float wv = __shfl_xor_sync(0xffffffffu, v, off);
            int   wi = __shfl_xor_sync(0xffffffffu, i, off);
            float wc = __shfl_xor_sync(0xffffffffu, c, off);
            if (wv > v) { c = fmaf(c, ex2a((v - wv) * a), wc); v = wv; i = wi; }
            else {
                c = fmaf(wc, ex2a((wv - v) * a), c);
                if (wv == v && wi < i) i = wi;
            }
            float wv2 = __shfl_xor_sync(0xffffffffu, v2, off);
            int   wi2 = __shfl_xor_sync(0xffffffffu, i2, off);
            if (wv2 > v2 || (wv2 == v2 && wi2 < i2)) { v2 = wv2; i2 = wi2; }
        }
        if (lane == 0) {
            // probs = exp2(l*a - max*a - log2(sum))
            fin_c = fmaf(-v, a, -log2f(c));
            out[b] = (float)((t == 0.0f) ? i : i2);
        }
    }
    __syncthreads();

    // ---- pass 2: probs = exp2(l*a + c) ----
    // REVERSE order (LIFO): the row tail is the freshest L2 content after
    // pass 1. x4 unrolled for per-thread MLP at 1 block/SM.
    const float c = fin_c;
    const float4* __restrict__ lrow4 = (const float4*)lrow;
    int j2 = tid + ((NV4 - 1 - tid) / NT) * NT;   // this thread's top chunk
    for (; j2 >= 3 * NT; j2 -= 4 * NT) {
        P2_BODY(j2)
        P2_BODY(j2 - NT)
        P2_BODY(j2 - 2 * NT)
        P2_BODY(j2 - 3 * NT)
    }
    for (; j2 >= 0; j2 -= NT) {
        P2_BODY(j2)
    }
}

extern "C" void kernel_launch(void* const* d_in, const int* in_sizes, int n_in,
                              void* d_out, int out_size) {
    const float* logits = (const float*)d_in[0];
    const float* temps  = (const float*)d_in[1];
    const float* noise  = (const float*)d_in[2];
    float* out = (float*)d_out;
    sampler_kernel<<<BB, NT>>>(logits, temps, noise, out);
}